// round 6
// baseline (speedup 1.0000x reference)
#include <cuda_runtime.h>
#include <cuda_fp16.h>
#include <cstdint>

#define BB 4
#define CC 384
#define QQ 384
#define HH 256
#define KK 256

#define ST 40   // smem row stride in halves (80B); 8-row ldmatrix addrs conflict-free

// ---------------------------------------------------------------- scratch
__device__ float g_term_h[BB*CC*KK];                 // term_h + b1 (exact fp32)
__device__ float g_term_u[BB*QQ*KK];                 // term_u     (exact fp32)
__device__ __align__(16) __half g_whu_h[KK*HH];      // W_hu fp16, [k][h] dense

__device__ __forceinline__ float lrelu(float x) {
    return fmaxf(x, 0.f) + 0.01f * fminf(x, 0.f);
}
__device__ __forceinline__ void mma16(float* d, const uint32_t* a, uint32_t b0, uint32_t b1) {
    asm volatile("mma.sync.aligned.m16n8k16.row.col.f32.f16.f16.f32 "
                 "{%0,%1,%2,%3}, {%4,%5,%6,%7}, {%8,%9}, {%0,%1,%2,%3};"
                 : "+f"(d[0]), "+f"(d[1]), "+f"(d[2]), "+f"(d[3])
                 : "r"(a[0]), "r"(a[1]), "r"(a[2]), "r"(a[3]), "r"(b0), "r"(b1));
}
__device__ __forceinline__ uint32_t smem_u32(const void* p) {
    uint32_t a;
    asm("{ .reg .u64 t; cvta.to.shared.u64 t, %1; cvt.u32.u64 %0, t; }" : "=r"(a) : "l"(p));
    return a;
}
#define LDSM_X4(r, a)                                                         \
    asm volatile("ldmatrix.sync.aligned.m8n8.x4.shared.b16 {%0,%1,%2,%3}, [%4];" \
                 : "=r"((r)[0]), "=r"((r)[1]), "=r"((r)[2]), "=r"((r)[3]) : "r"(a))
#define CP_ASYNC16(dst, src) \
    asm volatile("cp.async.cg.shared.global [%0], [%1], 16;" :: "r"(dst), "l"(src))
#define CP_COMMIT() asm volatile("cp.async.commit_group;" ::: "memory")
#define CP_WAIT0()  asm volatile("cp.async.wait_group 0;"  ::: "memory")

// ---------------------------------------------------------------- prep: pack W_hu fp16
__global__ void pack_whu_kernel(const float* __restrict__ w1) {
    const int k = blockIdx.x;
    const int h = threadIdx.x;
    g_whu_h[k * HH + h] = __float2half_rn(w1[(size_t)k * (3 * HH) + 2 * HH + h]);
}

// ---------------------------------------------------------------- fused term kernel
__global__ __launch_bounds__(256)
void term_fused_kernel(const float* __restrict__ h, const float* __restrict__ u,
                       const float* __restrict__ w1, const float* __restrict__ b1) {
    __shared__ float xs[16][HH];
    const int k = threadIdx.x;
    const bool is_h = blockIdx.x < (BB * CC / 16);
    const int r0 = (is_h ? blockIdx.x : blockIdx.x - BB * CC / 16) * 16;
    const float* x = is_h ? h : u;
    float* outb = is_h ? g_term_h : g_term_u;
    const int coloff = is_h ? 0 : HH;

    #pragma unroll
    for (int r = 0; r < 16; r++) xs[r][k] = x[(size_t)(r0 + r) * HH + k];
    __syncthreads();
    float acc[16];
    const float bv = is_h ? b1[k] : 0.f;
    #pragma unroll
    for (int r = 0; r < 16; r++) acc[r] = bv;
    const float4* wr = reinterpret_cast<const float4*>(w1 + (size_t)k * (3 * HH) + coloff);
    #pragma unroll 4
    for (int i = 0; i < HH / 4; i++) {
        float4 w = wr[i];
        #pragma unroll
        for (int r = 0; r < 16; r++) {
            float4 xv = *reinterpret_cast<const float4*>(&xs[r][4 * i]);
            acc[r] += xv.x * w.x + xv.y * w.y + xv.z * w.z + xv.w * w.w;
        }
    }
    #pragma unroll
    for (int r = 0; r < 16; r++) outb[(size_t)(r0 + r) * KK + k] = acc[r];
}

// ---------------------------------------------------------------- main fp16 mma kernel
// Per CTA: (b, c, q-tile 128). S[q,k] = sum_h (u[b,q,h]*h[b,c,h]) * W_hu[k,h]
// CTA tile M=128 x N=256, K chunks of 32 (m16n8k16), 2-stage cp.async pipe,
// ldmatrix fragment loads. 8 warps = 2M x 4N, warp tile 64x64.
#define AS0  0
#define AS1  10240
#define BS0  20480
#define BS1  40960
#define RED  61440
#define HCO  63488
#define THO  64512
#define W2O  65536
#define SMEM_BYTES 66560

__global__ __launch_bounds__(256, 1)
void main_mma_kernel(const float* __restrict__ hmat,
                     const float* __restrict__ u,
                     const float* __restrict__ w2,
                     const float* __restrict__ b2,
                     float* __restrict__ out)
{
    extern __shared__ char sm[];
    __half* As[2] = { reinterpret_cast<__half*>(sm + AS0), reinterpret_cast<__half*>(sm + AS1) };
    __half* Bs[2] = { reinterpret_cast<__half*>(sm + BS0), reinterpret_cast<__half*>(sm + BS1) };
    float* red  = reinterpret_cast<float*>(sm + RED);
    float* h_c  = reinterpret_cast<float*>(sm + HCO);
    float* th_s = reinterpret_cast<float*>(sm + THO);
    float* w2_s = reinterpret_cast<float*>(sm + W2O);

    const int tid = threadIdx.x;
    const int lid = tid & 31;
    const int wid = tid >> 5;
    const int g   = lid >> 2;
    const int t   = lid & 3;
    const int warpM = wid >> 2;      // 0..1
    const int warpN = wid & 3;       // 0..3

    const int b  = blockIdx.z;
    const int c  = blockIdx.y;
    const int q0 = blockIdx.x * 128;
    const int bc = b * CC + c;

    h_c[tid]  = hmat[(size_t)bc * HH + tid];
    th_s[tid] = g_term_h[(size_t)bc * KK + tid];
    w2_s[tid] = w2[tid];
    __syncthreads();

    // load coords
    const int arow[4] = { tid >> 3, (tid + 256) >> 3, (tid + 512) >> 3, (tid + 768) >> 3 };
    const int ac4 = tid & 7;
    const float* u_base = u + (size_t)(b * QQ + q0) * HH;
    const int brow[4] = { tid >> 2, (tid + 256) >> 2, (tid + 512) >> 2, (tid + 768) >> 2 };
    const int bseg = tid & 3;

    // ldmatrix base addresses (bytes), buf 0
    // A: lanes 0-7 rows R..R+7 @k0 | 8-15 rows R+8..15 @k0 | 16-23 R..R+7 @k8 | 24-31 R+8..15 @k8
    const uint32_t a_lm0 = smem_u32(As[0]) +
        (((warpM * 64 + (lid & 15)) * ST + ((lid >> 4) * 8)) * 2);
    // B: lanes 0-7 n..n+7 @k0 | 8-15 n..n+7 @k8 | 16-23 n+8..15 @k0 | 24-31 n+8..15 @k8
    const uint32_t b_lm0 = smem_u32(Bs[0]) +
        (((warpN * 64 + (lid & 7) + ((lid & 16) >> 1)) * ST + (((lid >> 3) & 1) * 8)) * 2);

    float acc[4][8][4];
    #pragma unroll
    for (int mt = 0; mt < 4; mt++)
        #pragma unroll
        for (int nt = 0; nt < 8; nt++)
            #pragma unroll
            for (int e = 0; e < 4; e++) acc[mt][nt][e] = 0.f;

    auto issue_B = [&](int ch, int buf) {
        const uint32_t bdst = smem_u32(Bs[buf]);
        #pragma unroll
        for (int i = 0; i < 4; i++)
            CP_ASYNC16(bdst + brow[i] * (ST * 2) + bseg * 16,
                       g_whu_h + (size_t)brow[i] * HH + ch * 32 + bseg * 8);
        CP_COMMIT();
    };
    auto load_A = [&](int ch, float4* aN) {
        #pragma unroll
        for (int i = 0; i < 4; i++)
            aN[i] = *reinterpret_cast<const float4*>(
                u_base + (size_t)arow[i] * HH + ch * 32 + ac4 * 4);
    };
    auto scale_store_A = [&](int ch, float4* aN, int buf) {
        const int kb = ac4 * 4;
        float4 hv = *reinterpret_cast<const float4*>(&h_c[ch * 32 + kb]);
        #pragma unroll
        for (int i = 0; i < 4; i++) {
            __half2 p0 = __floats2half2_rn(aN[i].x * hv.x, aN[i].y * hv.y);
            __half2 p1 = __floats2half2_rn(aN[i].z * hv.z, aN[i].w * hv.w);
            uint2 pk = { *reinterpret_cast<uint32_t*>(&p0), *reinterpret_cast<uint32_t*>(&p1) };
            *reinterpret_cast<uint2*>(&As[buf][arow[i] * ST + kb]) = pk;
        }
    };

    // prologue
    {
        float4 aN[4];
        load_A(0, aN);
        issue_B(0, 0);
        scale_store_A(0, aN, 0);
        CP_WAIT0();
        __syncthreads();
    }

    for (int ch = 0; ch < 8; ch++) {
        const int buf = ch & 1, nbuf = buf ^ 1;
        float4 aN[4];
        if (ch < 7) {
            issue_B(ch + 1, nbuf);
            load_A(ch + 1, aN);
        }

        const uint32_t a_lm = a_lm0 + buf * (AS1 - AS0);
        const uint32_t b_lm = b_lm0 + buf * (BS1 - BS0);
        #pragma unroll
        for (int s = 0; s < 2; s++) {
            uint32_t af[4][4];
            #pragma unroll
            for (int mt = 0; mt < 4; mt++)
                LDSM_X4(af[mt], a_lm + (mt * 16 * ST + s * 16) * 2);
            uint32_t bf[4][4];
            #pragma unroll
            for (int p = 0; p < 4; p++)
                LDSM_X4(bf[p], b_lm + (p * 16 * ST + s * 16) * 2);
            #pragma unroll
            for (int nt = 0; nt < 8; nt++) {
                const uint32_t b0 = bf[nt >> 1][(nt & 1) * 2 + 0];
                const uint32_t b1 = bf[nt >> 1][(nt & 1) * 2 + 1];
                #pragma unroll
                for (int mt = 0; mt < 4; mt++)
                    mma16(acc[mt][nt], af[mt], b0, b1);
            }
        }

        if (ch < 7) {
            scale_store_A(ch + 1, aN, nbuf);
            CP_WAIT0();
        }
        __syncthreads();
    }

    // ---- epilogue: +term_h +term_u, lrelu, weighted k-reduction ----
    #pragma unroll
    for (int mt = 0; mt < 4; mt++) {
        #pragma unroll
        for (int half = 0; half < 2; half++) {
            const int row = warpM * 64 + mt * 16 + half * 8 + g;
            const int q = q0 + row;
            const float* tu = g_term_u + (size_t)(b * QQ + q) * KK;
            float s = 0.f;
            #pragma unroll
            for (int nt = 0; nt < 8; nt++) {
                const int k = warpN * 64 + nt * 8 + 2 * t;
                float2 tv = *reinterpret_cast<const float2*>(tu + k);
                float v0 = acc[mt][nt][half * 2 + 0] + th_s[k]     + tv.x;
                float v1 = acc[mt][nt][half * 2 + 1] + th_s[k + 1] + tv.y;
                s += w2_s[k]     * lrelu(v0);
                s += w2_s[k + 1] * lrelu(v1);
            }
            s += __shfl_xor_sync(0xffffffffu, s, 1);
            s += __shfl_xor_sync(0xffffffffu, s, 2);
            if (t == 0) red[warpN * 128 + row] = s;
        }
    }
    __syncthreads();
    if (tid < 128) {
        float s = red[tid] + red[128 + tid] + red[256 + tid] + red[384 + tid] + b2[0];
        out[(size_t)bc * QQ + q0 + tid] = lrelu(s);
    }
}

// ---------------------------------------------------------------- launch
extern "C" void kernel_launch(void* const* d_in, const int* in_sizes, int n_in,
                              void* d_out, int out_size) {
    (void)in_sizes; (void)n_in; (void)out_size;
    const float* h_  = (const float*)d_in[0];
    const float* u_  = (const float*)d_in[1];
    const float* w1_ = (const float*)d_in[2];
    const float* b1_ = (const float*)d_in[3];
    const float* w2_ = (const float*)d_in[4];
    const float* b2_ = (const float*)d_in[5];
    float* out_ = (float*)d_out;

    cudaFuncSetAttribute(main_mma_kernel,
                         cudaFuncAttributeMaxDynamicSharedMemorySize, SMEM_BYTES);

    pack_whu_kernel<<<KK, HH>>>(w1_);
    term_fused_kernel<<<BB*CC/16 + BB*QQ/16, 256>>>(h_, u_, w1_, b1_);

    dim3 grid(QQ / 128, CC, BB);
    main_mma_kernel<<<grid, 256, SMEM_BYTES>>>(h_, u_, w2_, b2_, out_);
}

// round 7
// speedup vs baseline: 1.1531x; 1.1531x over previous
#include <cuda_runtime.h>
#include <cuda_fp16.h>
#include <cstdint>

#define BB 4
#define CC 384
#define QQ 384
#define HH 256
#define KK 256

#define ST 40   // smem row stride in halves (80B): fragment LDS conflict-free

// ---------------------------------------------------------------- scratch
__device__ float g_term_h[BB*CC*KK];                 // term_h + b1 (exact fp32)
__device__ float g_term_u[BB*QQ*KK];                 // term_u     (exact fp32)
__device__ __align__(16) __half g_whu_h[KK*HH];      // W_hu fp16, [k][h] dense

__device__ __forceinline__ float lrelu(float x) {
    return fmaxf(x, 0.f) + 0.01f * fminf(x, 0.f);
}
__device__ __forceinline__ void mma16(float* d, const uint32_t* a, uint32_t b0, uint32_t b1) {
    asm volatile("mma.sync.aligned.m16n8k16.row.col.f32.f16.f16.f32 "
                 "{%0,%1,%2,%3}, {%4,%5,%6,%7}, {%8,%9}, {%0,%1,%2,%3};"
                 : "+f"(d[0]), "+f"(d[1]), "+f"(d[2]), "+f"(d[3])
                 : "r"(a[0]), "r"(a[1]), "r"(a[2]), "r"(a[3]), "r"(b0), "r"(b1));
}
__device__ __forceinline__ uint32_t smem_u32(const void* p) {
    uint32_t a;
    asm("{ .reg .u64 t; cvta.to.shared.u64 t, %1; cvt.u32.u64 %0, t; }" : "=r"(a) : "l"(p));
    return a;
}
#define CP_ASYNC16(dst, src) \
    asm volatile("cp.async.cg.shared.global [%0], [%1], 16;" :: "r"(dst), "l"(src))
#define CP_COMMIT() asm volatile("cp.async.commit_group;" ::: "memory")
#define CP_WAIT0()  asm volatile("cp.async.wait_group 0;"  ::: "memory")

// ---------------------------------------------------------------- prep: pack W_hu fp16
__global__ void pack_whu_kernel(const float* __restrict__ w1) {
    const int k = blockIdx.x;
    const int h = threadIdx.x;
    g_whu_h[k * HH + h] = __float2half_rn(w1[(size_t)k * (3 * HH) + 2 * HH + h]);
}

// ---------------------------------------------------------------- fused term kernel
__global__ __launch_bounds__(256)
void term_fused_kernel(const float* __restrict__ h, const float* __restrict__ u,
                       const float* __restrict__ w1, const float* __restrict__ b1) {
    __shared__ float xs[16][HH];
    const int k = threadIdx.x;
    const bool is_h = blockIdx.x < (BB * CC / 16);
    const int r0 = (is_h ? blockIdx.x : blockIdx.x - BB * CC / 16) * 16;
    const float* x = is_h ? h : u;
    float* outb = is_h ? g_term_h : g_term_u;
    const int coloff = is_h ? 0 : HH;

    #pragma unroll
    for (int r = 0; r < 16; r++) xs[r][k] = x[(size_t)(r0 + r) * HH + k];
    __syncthreads();
    float acc[16];
    const float bv = is_h ? b1[k] : 0.f;
    #pragma unroll
    for (int r = 0; r < 16; r++) acc[r] = bv;
    const float4* wr = reinterpret_cast<const float4*>(w1 + (size_t)k * (3 * HH) + coloff);
    #pragma unroll 4
    for (int i = 0; i < HH / 4; i++) {
        float4 w = wr[i];
        #pragma unroll
        for (int r = 0; r < 16; r++) {
            float4 xv = *reinterpret_cast<const float4*>(&xs[r][4 * i]);
            acc[r] += xv.x * w.x + xv.y * w.y + xv.z * w.z + xv.w * w.w;
        }
    }
    #pragma unroll
    for (int r = 0; r < 16; r++) outb[(size_t)(r0 + r) * KK + k] = acc[r];
}

// ---------------------------------------------------------------- main fp16 mma kernel
// Per CTA: (b, c, q-tile 128). S[q,k] = sum_h (u[b,q,h]*h[b,c,h]) * W_hu[k,h]
// CTA tile M=128 x N=256, K chunks of 32 (m16n8k16), 2-stage cp.async pipe.
// 512 threads / 16 warps = 4M x 4N grid, warp tile 32x64, per-thread 2x8x4 acc.
#define AS0  0
#define AS1  10240
#define BS0  20480
#define BS1  40960
#define RED  61440
#define HCO  63488
#define THO  64512
#define W2O  65536
#define SMEM_BYTES 66560

__global__ __launch_bounds__(512, 1)
void main_mma_kernel(const float* __restrict__ hmat,
                     const float* __restrict__ u,
                     const float* __restrict__ w2,
                     const float* __restrict__ b2,
                     float* __restrict__ out)
{
    extern __shared__ char sm[];
    __half* As[2] = { reinterpret_cast<__half*>(sm + AS0), reinterpret_cast<__half*>(sm + AS1) };
    __half* Bs[2] = { reinterpret_cast<__half*>(sm + BS0), reinterpret_cast<__half*>(sm + BS1) };
    float* red  = reinterpret_cast<float*>(sm + RED);
    float* h_c  = reinterpret_cast<float*>(sm + HCO);
    float* th_s = reinterpret_cast<float*>(sm + THO);
    float* w2_s = reinterpret_cast<float*>(sm + W2O);

    const int tid = threadIdx.x;
    const int lid = tid & 31;
    const int wid = tid >> 5;
    const int g   = lid >> 2;        // 0..7
    const int t   = lid & 3;         // 0..3
    const int warpM = wid >> 2;      // 0..3  (32 q-rows each)
    const int warpN = wid & 3;       // 0..3  (64 k-cols each)

    const int b  = blockIdx.z;
    const int c  = blockIdx.y;
    const int q0 = blockIdx.x * 128;
    const int bc = b * CC + c;

    if (tid < 256) {
        h_c[tid]  = hmat[(size_t)bc * HH + tid];
        th_s[tid] = g_term_h[(size_t)bc * KK + tid];
        w2_s[tid] = w2[tid];
    }
    __syncthreads();

    // tile-load coords: A 1024 float4-segs over 2 iters; B 1024 16B-segs over 2 iters
    const int arow[2] = { tid >> 3, (tid + 512) >> 3 };
    const int ac4 = tid & 7;
    const float* u_base = u + (size_t)(b * QQ + q0) * HH;
    const int brow[2] = { tid >> 2, (tid + 512) >> 2 };
    const int bseg = tid & 3;

    float acc[2][8][4];
    #pragma unroll
    for (int mt = 0; mt < 2; mt++)
        #pragma unroll
        for (int nt = 0; nt < 8; nt++)
            #pragma unroll
            for (int e = 0; e < 4; e++) acc[mt][nt][e] = 0.f;

    auto issue_B = [&](int ch, int buf) {
        const uint32_t bdst = smem_u32(Bs[buf]);
        #pragma unroll
        for (int i = 0; i < 2; i++)
            CP_ASYNC16(bdst + brow[i] * (ST * 2) + bseg * 16,
                       g_whu_h + (size_t)brow[i] * HH + ch * 32 + bseg * 8);
        CP_COMMIT();
    };
    auto load_A = [&](int ch, float4* aN) {
        #pragma unroll
        for (int i = 0; i < 2; i++)
            aN[i] = *reinterpret_cast<const float4*>(
                u_base + (size_t)arow[i] * HH + ch * 32 + ac4 * 4);
    };
    auto scale_store_A = [&](int ch, float4* aN, int buf) {
        const int kb = ac4 * 4;
        float4 hv = *reinterpret_cast<const float4*>(&h_c[ch * 32 + kb]);
        #pragma unroll
        for (int i = 0; i < 2; i++) {
            __half2 p0 = __floats2half2_rn(aN[i].x * hv.x, aN[i].y * hv.y);
            __half2 p1 = __floats2half2_rn(aN[i].z * hv.z, aN[i].w * hv.w);
            uint2 pk = { *reinterpret_cast<uint32_t*>(&p0), *reinterpret_cast<uint32_t*>(&p1) };
            *reinterpret_cast<uint2*>(&As[buf][arow[i] * ST + kb]) = pk;
        }
    };

    // prologue
    {
        float4 aN[2];
        load_A(0, aN);
        issue_B(0, 0);
        scale_store_A(0, aN, 0);
        CP_WAIT0();
        __syncthreads();
    }

    for (int ch = 0; ch < 8; ch++) {
        const int buf = ch & 1, nbuf = buf ^ 1;
        float4 aN[2];
        if (ch < 7) {
            issue_B(ch + 1, nbuf);
            load_A(ch + 1, aN);
        }

        const uint32_t* Asu = reinterpret_cast<const uint32_t*>(As[buf]);  // half2 units
        const uint32_t* Bsu = reinterpret_cast<const uint32_t*>(Bs[buf]);
        #pragma unroll
        for (int s = 0; s < 2; s++) {
            const int k2 = s * 8;
            uint32_t af[2][4];
            #pragma unroll
            for (int mt = 0; mt < 2; mt++) {
                const int r0i = (warpM * 32 + mt * 16 + g) * (ST / 2) + k2 + t;
                af[mt][0] = Asu[r0i];
                af[mt][1] = Asu[r0i + 8 * (ST / 2)];
                af[mt][2] = Asu[r0i + 4];
                af[mt][3] = Asu[r0i + 8 * (ST / 2) + 4];
            }
            #pragma unroll
            for (int nt = 0; nt < 8; nt++) {
                const int nb = (warpN * 64 + nt * 8 + g) * (ST / 2) + k2 + t;
                const uint32_t b0 = Bsu[nb];
                const uint32_t b1 = Bsu[nb + 4];
                #pragma unroll
                for (int mt = 0; mt < 2; mt++)
                    mma16(acc[mt][nt], af[mt], b0, b1);
            }
        }

        if (ch < 7) {
            scale_store_A(ch + 1, aN, nbuf);
            CP_WAIT0();
        }
        __syncthreads();
    }

    // ---- epilogue: +term_h +term_u, lrelu, weighted k-reduction ----
    #pragma unroll
    for (int mt = 0; mt < 2; mt++) {
        #pragma unroll
        for (int half = 0; half < 2; half++) {
            const int row = warpM * 32 + mt * 16 + half * 8 + g;
            const int q = q0 + row;
            const float* tu = g_term_u + (size_t)(b * QQ + q) * KK;
            float s = 0.f;
            #pragma unroll
            for (int nt = 0; nt < 8; nt++) {
                const int k = warpN * 64 + nt * 8 + 2 * t;
                float2 tv = *reinterpret_cast<const float2*>(tu + k);
                float v0 = acc[mt][nt][half * 2 + 0] + th_s[k]     + tv.x;
                float v1 = acc[mt][nt][half * 2 + 1] + th_s[k + 1] + tv.y;
                s += w2_s[k]     * lrelu(v0);
                s += w2_s[k + 1] * lrelu(v1);
            }
            s += __shfl_xor_sync(0xffffffffu, s, 1);
            s += __shfl_xor_sync(0xffffffffu, s, 2);
            if (t == 0) red[warpN * 128 + row] = s;
        }
    }
    __syncthreads();
    if (tid < 128) {
        float s = red[tid] + red[128 + tid] + red[256 + tid] + red[384 + tid] + b2[0];
        out[(size_t)bc * QQ + q0 + tid] = lrelu(s);
    }
}

// ---------------------------------------------------------------- launch
extern "C" void kernel_launch(void* const* d_in, const int* in_sizes, int n_in,
                              void* d_out, int out_size) {
    (void)in_sizes; (void)n_in; (void)out_size;
    const float* h_  = (const float*)d_in[0];
    const float* u_  = (const float*)d_in[1];
    const float* w1_ = (const float*)d_in[2];
    const float* b1_ = (const float*)d_in[3];
    const float* w2_ = (const float*)d_in[4];
    const float* b2_ = (const float*)d_in[5];
    float* out_ = (float*)d_out;

    cudaFuncSetAttribute(main_mma_kernel,
                         cudaFuncAttributeMaxDynamicSharedMemorySize, SMEM_BYTES);

    pack_whu_kernel<<<KK, HH>>>(w1_);
    term_fused_kernel<<<BB*CC/16 + BB*QQ/16, 256>>>(h_, u_, w1_, b1_);

    dim3 grid(QQ / 128, CC, BB);
    main_mma_kernel<<<grid, 512, SMEM_BYTES>>>(h_, u_, w2_, b2_, out_);
}